// round 16
// baseline (speedup 1.0000x reference)
#include <cuda_runtime.h>
#include <cuda_fp16.h>
#include <cstdint>

// GrahamLoss: per-batch Frobenius distance between Gram matrices.
//   feat, feat_decod: [16, 128, 128, 128] fp32 -> out: [16] fp32
//
// Symmetric-gram fp16 mma.sync m16n8k16, fp32 accumulators (36 upper-tri
// 16x16 blocks = 56% of MACs). Flat balanced distribution: 296 CTAs (one
// 2-CTA/SM wave), each owns ~13.8 units (unit = 64-col k-chunk of one batch;
// enc pass, negate, dec pass => signed partial dec-enc). Epilogue
// RED-accumulates into L2-resident g_diff (590 KB). loss_kernel (16x4
// blocks) squares+weights+atomicAdds out[b] (zeroed by gram CTA 0), then
// re-zeroes g_diff for the next graph replay.

static constexpr int B_ = 16;
static constexpr int C_ = 128;
static constexpr long N_ = 16384;            // H*W
static constexpr int BK = 64;                // float cols per unit/tile
static constexpr int TILE_BYTES = C_ * BK * 2;    // 16384 (fp16 tile)
static constexpr int NSYM = 36;              // upper-tri 16x16 blocks
static constexpr int NCTA = 296;             // 2 CTAs x 148 SMs
static constexpr int UNITS = 4096;           // 16 b x 256 chunks

// 16 x 36 x 256 x 4B = 590 KB signed gram difference (L2-resident)
__device__ float g_diff[B_][NSYM][256];

// ---- symmetric tile bookkeeping (pair p owns tiles t=0..8) ----
__host__ __device__ constexpr int rowOf(int P, int t) {
    return t < 8 - P ? P : 7 - P;
}
__host__ __device__ constexpr int colOf(int P, int t) {
    return t < 8 - P ? P + t : (7 - P) + (t - (8 - P));
}
__host__ __device__ constexpr int cminOf(int P, int T0, int T1) {
    int m = 7;
    for (int t = T0; t < T1; t++) if (colOf(P, t) < m) m = colOf(P, t);
    return m;
}
__host__ __device__ constexpr int cmaxOf(int P, int T0, int T1) {
    int m = 0;
    for (int t = T0; t < T1; t++) if (colOf(P, t) > m) m = colOf(P, t);
    return m;
}

__device__ __forceinline__ uint32_t smem_u32(const void* p) {
    return (uint32_t)__cvta_generic_to_shared(p);
}
__device__ __forceinline__ uint32_t pack_f16x2(float lo, float hi) {
    uint32_t r;
    asm("cvt.rn.f16x2.f32 %0, %1, %2;" : "=r"(r) : "f"(hi), "f"(lo));
    return r;
}
__device__ __forceinline__ void ldsm4(uint32_t r[4], uint32_t addr) {
    asm volatile("ldmatrix.sync.aligned.m8n8.x4.shared.b16 {%0,%1,%2,%3}, [%4];"
                 : "=r"(r[0]), "=r"(r[1]), "=r"(r[2]), "=r"(r[3]) : "r"(addr));
}
__device__ __forceinline__ void mma16816(float* c, const uint32_t a[4],
                                         uint32_t b0, uint32_t b1) {
    asm volatile(
        "mma.sync.aligned.m16n8k16.row.col.f32.f16.f16.f32 "
        "{%0,%1,%2,%3}, {%4,%5,%6,%7}, {%8,%9}, {%0,%1,%2,%3};\n"
        : "+f"(c[0]), "+f"(c[1]), "+f"(c[2]), "+f"(c[3])
        : "r"(a[0]), "r"(a[1]), "r"(a[2]), "r"(a[3]), "r"(b0), "r"(b1));
}

// Compute one BK-wide smem tile's contribution to this warp's output tiles.
template <int P, int ROLE>
__device__ __forceinline__ void compute_tile(float* acc, uint32_t tb, int lane) {
    constexpr int T0 = ROLE ? 5 : 0, T1 = ROLE ? 9 : 5;
    constexpr int C0 = cminOf(P, T0, T1), C1 = cmaxOf(P, T0, T1);
    constexpr int NB = C1 - C0 + 1;
    constexpr bool NA0 = (T0 < 8 - P);   // any tile in row P?
    constexpr bool NA1 = (T1 > 8 - P);   // any tile in row 7-P?

    const int jj = lane >> 3, lr = lane & 7;
    const uint32_t lrx = (uint32_t)lr << 4;
    const uint32_t aRow = ((uint32_t)(jj & 1) << 3) + (uint32_t)lr;
    const uint32_t bRow = ((uint32_t)(jj >> 1) << 3) + (uint32_t)lr;
    const uint32_t aColBase = (uint32_t)(jj >> 1) << 4;
    const uint32_t bColBase = (uint32_t)(jj & 1) << 4;

    #pragma unroll
    for (int k16 = 0; k16 < 4; k16++) {
        const uint32_t cxa = (aColBase | ((uint32_t)k16 << 5)) ^ lrx;
        const uint32_t cxb = (bColBase | ((uint32_t)k16 << 5)) ^ lrx;

        uint32_t a0[4], a1[4];
        if constexpr (NA0) ldsm4(a0, tb + (16u * P + aRow) * 128u + cxa);
        if constexpr (NA1) ldsm4(a1, tb + (16u * (7 - P) + aRow) * 128u + cxa);

        uint32_t bb[NB][4];
        #pragma unroll
        for (int c = 0; c < NB; c++)
            ldsm4(bb[c], tb + (16u * (C0 + c) + bRow) * 128u + cxb);

        #pragma unroll
        for (int t = T0; t < T1; t++) {
            const uint32_t* A;
            if constexpr (NA0 && NA1) A = (rowOf(P, t) == P) ? a0 : a1;
            else if constexpr (NA0)   A = a0;
            else                      A = a1;
            uint32_t* B = bb[colOf(P, t) - C0];
            mma16816(acc + (t - T0) * 8,     A, B[0], B[1]);
            mma16816(acc + (t - T0) * 8 + 4, A, B[2], B[3]);
        }
    }
}

// RED-accumulate this warp's signed partial tiles into g_diff[b] (f-stride 256).
template <int P, int ROLE>
__device__ __forceinline__ void red_tiles(const float* acc, float* gp, int lane) {
    constexpr int T0 = ROLE ? 5 : 0, T1 = ROLE ? 9 : 5;
    const int gid = lane >> 2, tig = lane & 3;
    #pragma unroll
    for (int t = T0; t < T1; t++) {
        float* dst = gp + (P * 9 + t) * 256;
        const float* a = acc + (t - T0) * 8;
        atomicAdd(&dst[gid * 16 + 2 * tig],           a[0]);
        atomicAdd(&dst[gid * 16 + 2 * tig + 1],       a[1]);
        atomicAdd(&dst[(gid + 8) * 16 + 2 * tig],     a[2]);
        atomicAdd(&dst[(gid + 8) * 16 + 2 * tig + 1], a[3]);
        atomicAdd(&dst[gid * 16 + 8 + 2 * tig],           a[4]);
        atomicAdd(&dst[gid * 16 + 8 + 2 * tig + 1],       a[5]);
        atomicAdd(&dst[(gid + 8) * 16 + 8 + 2 * tig],     a[6]);
        atomicAdd(&dst[(gid + 8) * 16 + 8 + 2 * tig + 1], a[7]);
    }
}

#define DISPATCH(FN, ...)                                    \
    switch (code) {                                          \
        case 0: FN<0, 0>(__VA_ARGS__); break;                \
        case 1: FN<0, 1>(__VA_ARGS__); break;                \
        case 2: FN<1, 0>(__VA_ARGS__); break;                \
        case 3: FN<1, 1>(__VA_ARGS__); break;                \
        case 4: FN<2, 0>(__VA_ARGS__); break;                \
        case 5: FN<2, 1>(__VA_ARGS__); break;                \
        case 6: FN<3, 0>(__VA_ARGS__); break;                \
        case 7: FN<3, 1>(__VA_ARGS__); break;                \
    }

// One contiguous k-range of one batch: enc pass, negate, dec pass, RED out.
__device__ __forceinline__ void do_segment(
    const float* __restrict__ base_e, const float* __restrict__ base_d,
    int nt, float* __restrict__ gp, int code, int lane,
    const size_t* goff, const uint32_t* soff, uint32_t tbase, __half* tile0)
{
    float acc[40];
    #pragma unroll
    for (int i = 0; i < 40; i++) acc[i] = 0.0f;

    const int ntot = 2 * nt;

    float4 st[4][2];
    #pragma unroll
    for (int s = 0; s < 4; s++) {
        st[s][0] = *(const float4*)(base_e + goff[s]);
        st[s][1] = *(const float4*)(base_e + goff[s] + 4);
    }
    #pragma unroll
    for (int s = 0; s < 4; s++) {
        uint4 v;
        v.x = pack_f16x2(st[s][0].x, st[s][0].y);
        v.y = pack_f16x2(st[s][0].z, st[s][0].w);
        v.z = pack_f16x2(st[s][1].x, st[s][1].y);
        v.w = pack_f16x2(st[s][1].z, st[s][1].w);
        *(uint4*)((char*)tile0 + soff[s]) = v;
    }
    __syncthreads();

    for (int it = 0; it < ntot; ++it) {
        const bool more = (it + 1 < ntot);
        if (more) {
            const int nt2 = it + 1;
            const float* s0 = (nt2 < nt) ? (base_e + (size_t)nt2 * BK)
                                         : (base_d + (size_t)(nt2 - nt) * BK);
            #pragma unroll
            for (int s = 0; s < 4; s++) {
                st[s][0] = *(const float4*)(s0 + goff[s]);
                st[s][1] = *(const float4*)(s0 + goff[s] + 4);
            }
        }

        if (it == nt) {   // switch enc -> dec: final = dec - enc
            #pragma unroll
            for (int i = 0; i < 40; i++) acc[i] = -acc[i];
        }

        const uint32_t tb = tbase + (uint32_t)(it & 1) * (uint32_t)TILE_BYTES;
        DISPATCH(compute_tile, acc, tb, lane);

        if (more) {
            char* dstb = (char*)tile0 + ((it + 1) & 1) * TILE_BYTES;
            #pragma unroll
            for (int s = 0; s < 4; s++) {
                uint4 v;
                v.x = pack_f16x2(st[s][0].x, st[s][0].y);
                v.y = pack_f16x2(st[s][0].z, st[s][0].w);
                v.z = pack_f16x2(st[s][1].x, st[s][1].y);
                v.w = pack_f16x2(st[s][1].z, st[s][1].w);
                *(uint4*)(dstb + soff[s]) = v;
            }
        }
        __syncthreads();
    }

    DISPATCH(red_tiles, acc, gp, lane);
}

__global__ __launch_bounds__(256, 2)
void gram_kernel(const float* __restrict__ f_enc, const float* __restrict__ f_dec,
                 float* __restrict__ out) {
    const int cta  = blockIdx.x;
    const int tid  = threadIdx.x;
    const int lane = tid & 31;
    const int warp = tid >> 5;

    if (cta == 0 && tid < B_) out[tid] = 0.0f;   // loss_kernel atomicAdds later

    __shared__ __align__(1024) __half tile[2][C_ * BK];   // 2 x 16 KB, swizzled

    const int pairP = warp >> 1;
    const int role  = ((warp >> 2) ^ warp) & 1;   // balances HMMA across SMSPs
    const int code  = (pairP << 1) | role;

    // staging maps: store id h = tid + s*256 (4 uint4 stores/thread)
    size_t goff[4];
    uint32_t soff[4];
    #pragma unroll
    for (int s = 0; s < 4; s++) {
        const int h = tid + s * 256;
        const int row = h >> 3;
        const int colb = (h & 7) << 4;
        goff[s] = (size_t)row * N_ + (size_t)((h & 7) << 3);   // floats
        soff[s] = (uint32_t)row * 128u + ((uint32_t)colb ^ (uint32_t)((row & 7) << 4));
    }
    const uint32_t tbase = smem_u32(&tile[0][0]);

    // Flat unit range for this CTA (unit = 64-col chunk of one batch).
    const int u0 = (cta * UNITS) / NCTA;
    const int u1 = ((cta + 1) * UNITS) / NCTA;
    const int b0 = u0 >> 8;
    const int b1 = (u1 - 1) >> 8;

    {
        const int uend = (b1 > b0) ? ((b0 + 1) << 8) : u1;
        const int kc0  = u0 & 255;
        const size_t off = (size_t)b0 * C_ * N_ + (size_t)kc0 * BK;
        do_segment(f_enc + off, f_dec + off, uend - u0,
                   &g_diff[b0][0][0], code, lane, goff, soff, tbase,
                   &tile[0][0]);
    }
    if (b1 > b0) {
        const size_t off = (size_t)b1 * C_ * N_;
        do_segment(f_enc + off, f_dec + off, u1 - (b1 << 8),
                   &g_diff[b1][0][0], code, lane, goff, soff, tbase,
                   &tile[0][0]);
    }
}

__global__ __launch_bounds__(256, 1)
void loss_kernel(float* __restrict__ out) {
    const int b = blockIdx.x;        // batch
    const int q = blockIdx.y;        // pair P = q (9 tiles each)
    const int tid = threadIdx.x;
    float* __restrict__ base = &g_diff[b][0][0];

    float sum = 0.0f;
    #pragma unroll
    for (int ff = 0; ff < 9; ff++) {
        const float w = (ff == 0 || ff == 8 - q) ? 1.0f : 2.0f;   // diag x1
        const float v = base[(q * 9 + ff) * 256 + tid];
        sum += w * v * v;
    }

    __shared__ float red[256];
    red[tid] = sum;
    __syncthreads();
    #pragma unroll
    for (int o = 128; o > 0; o >>= 1) {
        if (tid < o) red[tid] += red[tid + o];
        __syncthreads();
    }
    if (tid == 0) {
        // denom = 4 * N^2 * C^2 = 2^44 (exact in fp32)
        const float scale = 1.0f / (4.0f * (float)N_ * (float)N_ * (float)C_ * (float)C_);
        atomicAdd(out + b, red[0] * scale);
    }

    // Re-zero this block's g_diff region for the next graph replay
    // (reads above completed before the first __syncthreads).
    #pragma unroll
    for (int ff = 0; ff < 9; ff++) base[(q * 9 + ff) * 256 + tid] = 0.0f;
}

extern "C" void kernel_launch(void* const* d_in, const int* in_sizes, int n_in,
                              void* d_out, int out_size) {
    const float* feat = (const float*)d_in[0];
    const float* feat_dec = (const float*)d_in[1];
    float* out = (float*)d_out;

    gram_kernel<<<NCTA, 256>>>(feat, feat_dec, out);
    loss_kernel<<<dim3(B_, 4), 256>>>(out);
}

// round 17
// speedup vs baseline: 1.5067x; 1.5067x over previous
#include <cuda_runtime.h>
#include <cuda_fp16.h>
#include <cstdint>

// GrahamLoss: per-batch Frobenius distance between Gram matrices.
//   feat, feat_decod: [16, 128, 128, 128] fp32 -> out: [16] fp32
//
// Symmetric-gram fp16 mma.sync m16n8k16, fp32 accumulators (36 upper-tri
// 16x16 blocks = 56% of MACs). 296 CTAs (one 2-CTA/SM wave), flat balanced
// k-units (enc pass, negate, dec pass => signed dec-enc). Quad-buffered
// dynamic smem (4 x 16 KB): ONE __syncthreads per 2 tiles. Epilogue RED-
// accumulates into L2-resident g_diff (590 KB). loss_kernel (16x4 blocks)
// squares+weights+atomicAdds out[b], then re-zeroes g_diff for replay.

static constexpr int B_ = 16;
static constexpr int C_ = 128;
static constexpr long N_ = 16384;            // H*W
static constexpr int BK = 64;                // float cols per unit/tile
static constexpr int TILE_BYTES = C_ * BK * 2;    // 16384 (fp16 tile)
static constexpr int NSYM = 36;              // upper-tri 16x16 blocks
static constexpr int NCTA = 296;             // 2 CTAs x 148 SMs
static constexpr int UNITS = 4096;           // 16 b x 256 chunks
static constexpr int SMEM_BYTES = 4 * TILE_BYTES + 128;  // quad buffer + align

// 16 x 36 x 256 x 4B = 590 KB signed gram difference (L2-resident)
__device__ float g_diff[B_][NSYM][256];

// ---- symmetric tile bookkeeping (pair p owns tiles t=0..8) ----
__host__ __device__ constexpr int rowOf(int P, int t) {
    return t < 8 - P ? P : 7 - P;
}
__host__ __device__ constexpr int colOf(int P, int t) {
    return t < 8 - P ? P + t : (7 - P) + (t - (8 - P));
}
__host__ __device__ constexpr int cminOf(int P, int T0, int T1) {
    int m = 7;
    for (int t = T0; t < T1; t++) if (colOf(P, t) < m) m = colOf(P, t);
    return m;
}
__host__ __device__ constexpr int cmaxOf(int P, int T0, int T1) {
    int m = 0;
    for (int t = T0; t < T1; t++) if (colOf(P, t) > m) m = colOf(P, t);
    return m;
}

__device__ __forceinline__ uint32_t smem_u32(const void* p) {
    return (uint32_t)__cvta_generic_to_shared(p);
}
__device__ __forceinline__ uint32_t pack_f16x2(float lo, float hi) {
    uint32_t r;
    asm("cvt.rn.f16x2.f32 %0, %1, %2;" : "=r"(r) : "f"(hi), "f"(lo));
    return r;
}
__device__ __forceinline__ void ldsm4(uint32_t r[4], uint32_t addr) {
    asm volatile("ldmatrix.sync.aligned.m8n8.x4.shared.b16 {%0,%1,%2,%3}, [%4];"
                 : "=r"(r[0]), "=r"(r[1]), "=r"(r[2]), "=r"(r[3]) : "r"(addr));
}
__device__ __forceinline__ void mma16816(float* c, const uint32_t a[4],
                                         uint32_t b0, uint32_t b1) {
    asm volatile(
        "mma.sync.aligned.m16n8k16.row.col.f32.f16.f16.f32 "
        "{%0,%1,%2,%3}, {%4,%5,%6,%7}, {%8,%9}, {%0,%1,%2,%3};\n"
        : "+f"(c[0]), "+f"(c[1]), "+f"(c[2]), "+f"(c[3])
        : "r"(a[0]), "r"(a[1]), "r"(a[2]), "r"(a[3]), "r"(b0), "r"(b1));
}

// Compute one BK-wide smem tile's contribution to this warp's output tiles.
template <int P, int ROLE>
__device__ __forceinline__ void compute_tile(float* acc, uint32_t tb, int lane) {
    constexpr int T0 = ROLE ? 5 : 0, T1 = ROLE ? 9 : 5;
    constexpr int C0 = cminOf(P, T0, T1), C1 = cmaxOf(P, T0, T1);
    constexpr int NB = C1 - C0 + 1;
    constexpr bool NA0 = (T0 < 8 - P);   // any tile in row P?
    constexpr bool NA1 = (T1 > 8 - P);   // any tile in row 7-P?

    const int jj = lane >> 3, lr = lane & 7;
    const uint32_t lrx = (uint32_t)lr << 4;
    const uint32_t aRow = ((uint32_t)(jj & 1) << 3) + (uint32_t)lr;
    const uint32_t bRow = ((uint32_t)(jj >> 1) << 3) + (uint32_t)lr;
    const uint32_t aColBase = (uint32_t)(jj >> 1) << 4;
    const uint32_t bColBase = (uint32_t)(jj & 1) << 4;

    #pragma unroll
    for (int k16 = 0; k16 < 4; k16++) {
        const uint32_t cxa = (aColBase | ((uint32_t)k16 << 5)) ^ lrx;
        const uint32_t cxb = (bColBase | ((uint32_t)k16 << 5)) ^ lrx;

        uint32_t a0[4], a1[4];
        if constexpr (NA0) ldsm4(a0, tb + (16u * P + aRow) * 128u + cxa);
        if constexpr (NA1) ldsm4(a1, tb + (16u * (7 - P) + aRow) * 128u + cxa);

        uint32_t bb[NB][4];
        #pragma unroll
        for (int c = 0; c < NB; c++)
            ldsm4(bb[c], tb + (16u * (C0 + c) + bRow) * 128u + cxb);

        #pragma unroll
        for (int t = T0; t < T1; t++) {
            const uint32_t* A;
            if constexpr (NA0 && NA1) A = (rowOf(P, t) == P) ? a0 : a1;
            else if constexpr (NA0)   A = a0;
            else                      A = a1;
            uint32_t* B = bb[colOf(P, t) - C0];
            mma16816(acc + (t - T0) * 8,     A, B[0], B[1]);
            mma16816(acc + (t - T0) * 8 + 4, A, B[2], B[3]);
        }
    }
}

// RED-accumulate this warp's signed partial tiles into g_diff[b] (f-stride 256).
template <int P, int ROLE>
__device__ __forceinline__ void red_tiles(const float* acc, float* gp, int lane) {
    constexpr int T0 = ROLE ? 5 : 0, T1 = ROLE ? 9 : 5;
    const int gid = lane >> 2, tig = lane & 3;
    #pragma unroll
    for (int t = T0; t < T1; t++) {
        float* dst = gp + (P * 9 + t) * 256;
        const float* a = acc + (t - T0) * 8;
        atomicAdd(&dst[gid * 16 + 2 * tig],           a[0]);
        atomicAdd(&dst[gid * 16 + 2 * tig + 1],       a[1]);
        atomicAdd(&dst[(gid + 8) * 16 + 2 * tig],     a[2]);
        atomicAdd(&dst[(gid + 8) * 16 + 2 * tig + 1], a[3]);
        atomicAdd(&dst[gid * 16 + 8 + 2 * tig],           a[4]);
        atomicAdd(&dst[gid * 16 + 8 + 2 * tig + 1],       a[5]);
        atomicAdd(&dst[(gid + 8) * 16 + 8 + 2 * tig],     a[6]);
        atomicAdd(&dst[(gid + 8) * 16 + 8 + 2 * tig + 1], a[7]);
    }
}

#define DISPATCH(FN, ...)                                    \
    switch (code) {                                          \
        case 0: FN<0, 0>(__VA_ARGS__); break;                \
        case 1: FN<0, 1>(__VA_ARGS__); break;                \
        case 2: FN<1, 0>(__VA_ARGS__); break;                \
        case 3: FN<1, 1>(__VA_ARGS__); break;                \
        case 4: FN<2, 0>(__VA_ARGS__); break;                \
        case 5: FN<2, 1>(__VA_ARGS__); break;                \
        case 6: FN<3, 0>(__VA_ARGS__); break;                \
        case 7: FN<3, 1>(__VA_ARGS__); break;                \
    }

__device__ __forceinline__ void ldg_tile(const float* __restrict__ s0,
                                         const size_t* goff, float4 st[4][2]) {
    #pragma unroll
    for (int s = 0; s < 4; s++) {
        st[s][0] = *(const float4*)(s0 + goff[s]);
        st[s][1] = *(const float4*)(s0 + goff[s] + 4);
    }
}
__device__ __forceinline__ void sts_tile(const float4 st[4][2],
                                         const uint32_t* soff, char* dstb) {
    #pragma unroll
    for (int s = 0; s < 4; s++) {
        uint4 v;
        v.x = pack_f16x2(st[s][0].x, st[s][0].y);
        v.y = pack_f16x2(st[s][0].z, st[s][0].w);
        v.z = pack_f16x2(st[s][1].x, st[s][1].y);
        v.w = pack_f16x2(st[s][1].z, st[s][1].w);
        *(uint4*)(dstb + soff[s]) = v;
    }
}

// One contiguous k-range of one batch: enc pass, negate, dec pass, RED out.
// Quad-buffered: pair j computes buffers (j&1)*2, (j&1)*2+1 while staging the
// next pair into the other two; ONE __syncthreads per pair.
__device__ __forceinline__ void do_segment(
    const float* __restrict__ base_e, const float* __restrict__ base_d,
    int nt, float* __restrict__ gp, int code, int lane,
    const size_t* goff, const uint32_t* soff, uint32_t tbase, char* tile0)
{
    float acc[40];
    #pragma unroll
    for (int i = 0; i < 40; i++) acc[i] = 0.0f;

    const int npair = nt;   // ntot = 2*nt tiles -> nt pairs

    // ---- prologue: tiles 0,1 into buffers 0,1 ----
    float4 st[4][2];
    ldg_tile(base_e, goff, st);
    sts_tile(st, soff, tile0);
    const float* s1 = (1 < nt) ? (base_e + BK) : base_d;
    ldg_tile(s1, goff, st);
    sts_tile(st, soff, tile0 + TILE_BYTES);
    __syncthreads();

    for (int j = 0; j < npair; ++j) {
        const bool more = (j + 1 < npair);
        const uint32_t bufo = (uint32_t)(j & 1) * 2u * (uint32_t)TILE_BYTES;
        char* dst0 = tile0 + (((j + 1) & 1) * 2) * TILE_BYTES;

        if (more) {
            const int m = 2 * j + 2;
            const float* s = (m < nt) ? (base_e + (size_t)m * BK)
                                      : (base_d + (size_t)(m - nt) * BK);
            ldg_tile(s, goff, st);
        }

        if (2 * j == nt) {   // enc -> dec switch at even tile
            #pragma unroll
            for (int i = 0; i < 40; i++) acc[i] = -acc[i];
        }
        DISPATCH(compute_tile, acc, tbase + bufo, lane);

        if (more) {
            sts_tile(st, soff, dst0);
            const int m = 2 * j + 3;
            const float* s = (m < nt) ? (base_e + (size_t)m * BK)
                                      : (base_d + (size_t)(m - nt) * BK);
            ldg_tile(s, goff, st);
        }

        if (2 * j + 1 == nt) {   // enc -> dec switch at odd tile
            #pragma unroll
            for (int i = 0; i < 40; i++) acc[i] = -acc[i];
        }
        DISPATCH(compute_tile, acc, tbase + bufo + (uint32_t)TILE_BYTES, lane);

        if (more) sts_tile(st, soff, dst0 + TILE_BYTES);
        __syncthreads();
    }

    DISPATCH(red_tiles, acc, gp, lane);
}

__global__ __launch_bounds__(256, 2)
void gram_kernel(const float* __restrict__ f_enc, const float* __restrict__ f_dec,
                 float* __restrict__ out) {
    const int cta  = blockIdx.x;
    const int tid  = threadIdx.x;
    const int lane = tid & 31;
    const int warp = tid >> 5;

    if (cta == 0 && tid < B_) out[tid] = 0.0f;   // loss_kernel atomicAdds later

    extern __shared__ char dynsmem[];
    // 128-byte align so the xor swizzle's bank pattern is preserved.
    char* tile0 = (char*)(((uintptr_t)dynsmem + 127) & ~(uintptr_t)127);

    const int pairP = warp >> 1;
    const int role  = ((warp >> 2) ^ warp) & 1;   // balances HMMA across SMSPs
    const int code  = (pairP << 1) | role;

    // staging maps: store id h = tid + s*256 (4 uint4 stores/thread)
    size_t goff[4];
    uint32_t soff[4];
    #pragma unroll
    for (int s = 0; s < 4; s++) {
        const int h = tid + s * 256;
        const int row = h >> 3;
        const int colb = (h & 7) << 4;
        goff[s] = (size_t)row * N_ + (size_t)((h & 7) << 3);   // floats
        soff[s] = (uint32_t)row * 128u + ((uint32_t)colb ^ (uint32_t)((row & 7) << 4));
    }
    const uint32_t tbase = smem_u32(tile0);

    // Flat unit range for this CTA (unit = 64-col chunk of one batch).
    const int u0 = (cta * UNITS) / NCTA;
    const int u1 = ((cta + 1) * UNITS) / NCTA;
    const int b0 = u0 >> 8;
    const int b1 = (u1 - 1) >> 8;

    {
        const int uend = (b1 > b0) ? ((b0 + 1) << 8) : u1;
        const int kc0  = u0 & 255;
        const size_t off = (size_t)b0 * C_ * N_ + (size_t)kc0 * BK;
        do_segment(f_enc + off, f_dec + off, uend - u0,
                   &g_diff[b0][0][0], code, lane, goff, soff, tbase, tile0);
    }
    if (b1 > b0) {
        const size_t off = (size_t)b1 * C_ * N_;
        do_segment(f_enc + off, f_dec + off, u1 - (b1 << 8),
                   &g_diff[b1][0][0], code, lane, goff, soff, tbase, tile0);
    }
}

__global__ __launch_bounds__(256, 1)
void loss_kernel(float* __restrict__ out) {
    const int b = blockIdx.x;        // batch
    const int q = blockIdx.y;        // pair P = q (9 tiles each)
    const int tid = threadIdx.x;
    float* __restrict__ base = &g_diff[b][0][0];

    float sum = 0.0f;
    #pragma unroll
    for (int ff = 0; ff < 9; ff++) {
        const float w = (ff == 0 || ff == 8 - q) ? 1.0f : 2.0f;   // diag x1
        const float v = base[(q * 9 + ff) * 256 + tid];
        sum += w * v * v;
    }

    __shared__ float red[256];
    red[tid] = sum;
    __syncthreads();
    #pragma unroll
    for (int o = 128; o > 0; o >>= 1) {
        if (tid < o) red[tid] += red[tid + o];
        __syncthreads();
    }
    if (tid == 0) {
        // denom = 4 * N^2 * C^2 = 2^44 (exact in fp32)
        const float scale = 1.0f / (4.0f * (float)N_ * (float)N_ * (float)C_ * (float)C_);
        atomicAdd(out + b, red[0] * scale);
    }

    // Re-zero this block's g_diff region for the next graph replay
    // (reads above completed before the first __syncthreads).
    #pragma unroll
    for (int ff = 0; ff < 9; ff++) base[(q * 9 + ff) * 256 + tid] = 0.0f;
}

extern "C" void kernel_launch(void* const* d_in, const int* in_sizes, int n_in,
                              void* d_out, int out_size) {
    const float* feat = (const float*)d_in[0];
    const float* feat_dec = (const float*)d_in[1];
    float* out = (float*)d_out;

    // Opt in to >48 KB dynamic smem (idempotent; immediate host-side call,
    // not a stream operation -> safe under graph capture).
    cudaFuncSetAttribute(gram_kernel,
                         cudaFuncAttributeMaxDynamicSharedMemorySize, SMEM_BYTES);

    gram_kernel<<<NCTA, 256, SMEM_BYTES>>>(feat, feat_dec, out);
    loss_kernel<<<dim3(B_, 4), 256>>>(out);
}